// round 2
// baseline (speedup 1.0000x reference)
#include <cuda_runtime.h>
#include <cstdint>

// ---------------- problem constants ----------------
#define NROW 8192
#define KDIM 64
#define NAUG 72
#define NTILES 9                 // 72 / 8
#define TILE_M 128
#define KC 32                    // K per chunk
#define SPLITS 4
#define KSPLIT (NROW / SPLITS)   // 2048
#define NCHUNK (KSPLIT / KC)     // 64
#define NTHREADS 128             // 4 warps, each warp: 32 M-rows x 72 N-cols
#define MTILES (NROW / TILE_M)   // 64
#define NGCHUNK (NROW / KC)      // 256 global k-chunks
#define ASTRIDE 44               // padded A row stride in floats (conflict-free + 16B-aligned)
#define BCHUNK (NTILES * KC * 8) // 2304 floats per B chunk

// ---------------- device scratch (no allocs allowed) ----------------
__device__ float g_sq[NROW];
__device__ __align__(16) float g_yaugB[NGCHUNK * BCHUNK];  // 589824 floats (2.36 MB), tf32-rounded
__device__ float g_part[MTILES * SPLITS];

// ---------------- small helpers ----------------
__device__ __forceinline__ uint32_t smem_to_u32(const void* p) {
    uint32_t a;
    asm("{ .reg .u64 t; cvta.to.shared.u64 t, %1; cvt.u32.u64 %0, t; }" : "=r"(a) : "l"(p));
    return a;
}
__device__ __forceinline__ uint32_t f2tf_rna(float x) {   // round-to-nearest tf32 (unbiased)
    uint32_t r;
    asm("cvt.rna.tf32.f32 %0, %1;" : "=r"(r) : "f"(x));
    return r;
}
__device__ __forceinline__ void cpa16(uint32_t dst_smem, const void* src_gmem) {
    asm volatile("cp.async.cg.shared.global [%0], [%1], 16;" :: "r"(dst_smem), "l"(src_gmem));
}
#define CP_COMMIT() asm volatile("cp.async.commit_group;" ::: "memory")
#define CP_WAIT1()  asm volatile("cp.async.wait_group 1;" ::: "memory")
#define CP_WAIT0()  asm volatile("cp.async.wait_group 0;" ::: "memory")

__device__ __forceinline__ void mma_tf32(float* c, uint32_t a0, uint32_t a1, uint32_t a2,
                                         uint32_t a3, uint32_t b0, uint32_t b1) {
    asm volatile(
        "mma.sync.aligned.m16n8k8.row.col.f32.tf32.tf32.f32 "
        "{%0,%1,%2,%3},{%4,%5,%6,%7},{%8,%9},{%0,%1,%2,%3};"
        : "+f"(c[0]), "+f"(c[1]), "+f"(c[2]), "+f"(c[3])
        : "r"(a0), "r"(a1), "r"(a2), "r"(a3), "r"(b0), "r"(b1));
}

// ---------------- SMEM layout (dynamic, bytes) ----------------
#define SMEM_A0   0
#define SMEM_A1   (TILE_M * ASTRIDE * 4)                  // 22528
#define SMEM_B0   (2 * TILE_M * ASTRIDE * 4)              // 45056
#define SMEM_B1   (SMEM_B0 + BCHUNK * 4)                  // 54272
#define SMEM_RED  (SMEM_B1 + BCHUNK * 4)                  // 63488
#define SMEM_TOTAL (SMEM_RED + 64)                        // 63552

// ---------------- prep kernels ----------------
__global__ void prep_sq(const float* __restrict__ Y) {
    int w = (blockIdx.x * blockDim.x + threadIdx.x) >> 5;
    int lane = threadIdx.x & 31;
    if (w >= NROW) return;
    const float* yr = Y + (size_t)w * KDIM;
    float v0 = yr[lane], v1 = yr[lane + 32];
    float s = v0 * v0 + v1 * v1;
#pragma unroll
    for (int o = 16; o; o >>= 1) s += __shfl_xor_sync(0xffffffffu, s, o);
    if (lane == 0) g_sq[w] = s;
}

// Build Yaug in n-tile-blocked layout: [gchunk][nt][k(32)][n(8)], tf32-rounded fp32.
__global__ void prep_yaugB(const float* __restrict__ Y) {
    int idx = blockIdx.x * blockDim.x + threadIdx.x;
    if (idx >= NGCHUNK * BCHUNK) return;
    int gc  = idx / BCHUNK;
    int rem = idx - gc * BCHUNK;
    int nt  = rem >> 8;           // /256
    int k   = (rem >> 3) & 31;
    int n8  = rem & 7;
    int kg  = gc * KC + k;        // global k (row index of Yaug)
    int n   = nt * 8 + n8;        // augmented column
    float v;
    if (n < KDIM)            v = Y[(size_t)kg * KDIM + n];
    else if (n == KDIM)      v = 1.0f;
    else if (n == KDIM + 1)  v = g_sq[kg];
    else                     v = 0.0f;
    g_yaugB[idx] = __uint_as_float(f2tf_rna(v));
}

// ---------------- main kernel ----------------
__global__ __launch_bounds__(NTHREADS)
void spectral_main(const float* __restrict__ W, const float* __restrict__ Y) {
    extern __shared__ __align__(16) char smem[];
    float* smf = reinterpret_cast<float*>(smem);
    const uint32_t sb = smem_to_u32(smem);

    const int tid  = threadIdx.x;
    const int wid  = tid >> 5;
    const int lane = tid & 31;
    const int g    = lane >> 2;   // 0..7
    const int tg   = lane & 3;    // 0..3
    const int m0   = blockIdx.x * TILE_M;
    const int kbase = blockIdx.y * KSPLIT;

    float acc[2][NTILES][4];
#pragma unroll
    for (int mf = 0; mf < 2; ++mf)
#pragma unroll
        for (int nt = 0; nt < NTILES; ++nt)
#pragma unroll
            for (int q = 0; q < 4; ++q) acc[mf][nt][q] = 0.0f;

    // ---- async load of one chunk into buffer (t&1) ----
    auto load_chunk = [&](int t) {
        const uint32_t ab = sb + ((t & 1) ? SMEM_A1 : SMEM_A0);
        const uint32_t bb = sb + ((t & 1) ? SMEM_B1 : SMEM_B0);
        const int k0 = kbase + t * KC;
        // A: W tile 128 x 32 fp32 = 1024 float4; 8 per thread
#pragma unroll
        for (int j = 0; j < 8; ++j) {
            int f  = tid + j * NTHREADS;
            int r  = f >> 3, c4 = f & 7;
            cpa16(ab + (uint32_t)(r * ASTRIDE + c4 * 4) * 4,
                  W + (size_t)(m0 + r) * NROW + k0 + c4 * 4);
        }
        // B: pre-blocked Yaug chunk, 2304 floats = 576 float4
        const float* bsrc = g_yaugB + (size_t)(k0 >> 5) * BCHUNK;
#pragma unroll
        for (int j = 0; j < 5; ++j) {
            int f = tid + j * NTHREADS;
            if (f < 576) cpa16(bb + (uint32_t)f * 16, bsrc + f * 4);
        }
        CP_COMMIT();
    };

    load_chunk(0);

    for (int t = 0; t < NCHUNK; ++t) {
        if (t + 1 < NCHUNK) { load_chunk(t + 1); CP_WAIT1(); }
        else                { CP_WAIT0(); }
        __syncthreads();

        const float* abuf = smf + ((t & 1) ? SMEM_A1 : SMEM_A0) / 4;
        const float* bbuf = smf + ((t & 1) ? SMEM_B1 : SMEM_B0) / 4;

#pragma unroll
        for (int ks = 0; ks < KC / 8; ++ks) {
            // A fragments (W), rounded to tf32 rna (unbiased)
            uint32_t a[2][4];
#pragma unroll
            for (int mf = 0; mf < 2; ++mf) {
                int rbase = wid * 32 + mf * 16;
                int cbase = ks * 8 + tg;
                a[mf][0] = f2tf_rna(abuf[(rbase + g) * ASTRIDE + cbase]);
                a[mf][1] = f2tf_rna(abuf[(rbase + g + 8) * ASTRIDE + cbase]);
                a[mf][2] = f2tf_rna(abuf[(rbase + g) * ASTRIDE + cbase + 4]);
                a[mf][3] = f2tf_rna(abuf[(rbase + g + 8) * ASTRIDE + cbase + 4]);
            }
            // B fragments (Yaug, already tf32-rounded bits)
#pragma unroll
            for (int nt = 0; nt < NTILES; ++nt) {
                int bidx = nt * 256 + (ks * 8 + tg) * 8 + g;
                uint32_t b0 = __float_as_uint(bbuf[bidx]);
                uint32_t b1 = __float_as_uint(bbuf[bidx + 32]);
                mma_tf32(acc[0][nt], a[0][0], a[0][1], a[0][2], a[0][3], b0, b1);
                mma_tf32(acc[1][nt], a[1][0], a[1][1], a[1][2], a[1][3], b0, b1);
            }
        }
        __syncthreads();
    }

    // ---- epilogue: partial = sum over Z fragment elements * coef ----
    // Z element (row i, col c): coef = -2*Y[i,c] (c<64), sq_i (c==64), 1 (c==65), 0 (c>=66)
    float partial = 0.0f;
#pragma unroll
    for (int mf = 0; mf < 2; ++mf) {
#pragma unroll
        for (int half = 0; half < 2; ++half) {
            int i = m0 + wid * 32 + mf * 16 + half * 8 + g;
            const float* yr = Y + (size_t)i * KDIM;
            float s = 0.0f;
#pragma unroll
            for (int nt = 0; nt < 8; ++nt) {
                int col = nt * 8 + tg * 2;
                s = fmaf(yr[col],     acc[mf][nt][half * 2 + 0], s);
                s = fmaf(yr[col + 1], acc[mf][nt][half * 2 + 1], s);
            }
            float e = -2.0f * s;
            if (tg == 0) {  // nt=8 holds cols 64..71; only tg==0 sees cols 64,65
                e = fmaf(g_sq[i], acc[mf][8][half * 2 + 0], e);
                e += acc[mf][8][half * 2 + 1];
            }
            partial += e;
        }
    }
#pragma unroll
    for (int o = 16; o; o >>= 1) partial += __shfl_xor_sync(0xffffffffu, partial, o);
    float* red = reinterpret_cast<float*>(smem + SMEM_RED);
    if (lane == 0) red[wid] = partial;
    __syncthreads();
    if (tid == 0)
        g_part[blockIdx.y * MTILES + blockIdx.x] = red[0] + red[1] + red[2] + red[3];
}

// ---------------- final deterministic reduction ----------------
__global__ void final_reduce(float* __restrict__ out) {
    float s = g_part[threadIdx.x];  // exactly 256 entries, 256 threads
#pragma unroll
    for (int o = 16; o; o >>= 1) s += __shfl_xor_sync(0xffffffffu, s, o);
    __shared__ float r[8];
    if ((threadIdx.x & 31) == 0) r[threadIdx.x >> 5] = s;
    __syncthreads();
    if (threadIdx.x == 0) {
        float t = 0.0f;
#pragma unroll
        for (int j = 0; j < 8; ++j) t += r[j];
        out[0] = t * (1.0f / (2.0f * (float)NROW));
    }
}

// ---------------- launch ----------------
extern "C" void kernel_launch(void* const* d_in, const int* in_sizes, int n_in,
                              void* d_out, int out_size) {
    const float* W;
    const float* Y;
    if (in_sizes[0] == NROW * NROW) {
        W = (const float*)d_in[0];
        Y = (const float*)d_in[1];
    } else {
        Y = (const float*)d_in[0];
        W = (const float*)d_in[1];
    }
    cudaFuncSetAttribute(spectral_main, cudaFuncAttributeMaxDynamicSharedMemorySize, SMEM_TOTAL);

    prep_sq<<<NROW / 8, 256>>>(Y);
    prep_yaugB<<<(NGCHUNK * BCHUNK + 255) / 256, 256>>>(Y);
    spectral_main<<<dim3(MTILES, SPLITS), NTHREADS, SMEM_TOTAL>>>(W, Y);
    final_reduce<<<1, 256>>>((float*)d_out);
}

// round 3
// speedup vs baseline: 1.3578x; 1.3578x over previous
#include <cuda_runtime.h>
#include <cuda_bf16.h>
#include <cstdint>

// ---------------- problem constants ----------------
#define NROW 8192
#define KDIM 64
#define NAUG 72
#define NTILES 9                 // 72 / 8
#define TILE_M 128
#define KC 32                    // K per chunk (2 x k16 fragments)
#define SPLITS 8
#define KSPLIT (NROW / SPLITS)   // 1024
#define NCHUNK (KSPLIT / KC)     // 32
#define NTHREADS 128
#define MTILES (NROW / TILE_M)   // 64
#define NGCHUNK (NROW / KC)      // 256 global k-chunks
#define ASTRIDE 40               // padded A row stride in floats (phase-conflict-free)
#define BCH_BYTES (2 * NTILES * 256)   // 4608 bytes per B chunk (2 k16frags x 9 nt x 32 lanes x 8B)
#define NPART (MTILES * SPLITS)  // 512

// ---------------- device scratch ----------------
__device__ float g_sq[NROW];
__device__ __align__(16) unsigned char g_yaugB[NGCHUNK * BCH_BYTES];  // 1.18 MB, fragment-packed bf16
__device__ float g_part[NPART];
__device__ unsigned int g_cnt = 0;

// ---------------- helpers ----------------
__device__ __forceinline__ uint32_t smem_to_u32(const void* p) {
    uint32_t a;
    asm("{ .reg .u64 t; cvta.to.shared.u64 t, %1; cvt.u32.u64 %0, t; }" : "=r"(a) : "l"(p));
    return a;
}
__device__ __forceinline__ uint32_t pack_bf16x2(float lo, float hi) {
    uint32_t r;
    asm("cvt.rn.bf16x2.f32 %0, %1, %2;" : "=r"(r) : "f"(hi), "f"(lo));
    return r;
}
__device__ __forceinline__ void cpa16(uint32_t dst_smem, const void* src_gmem) {
    asm volatile("cp.async.cg.shared.global [%0], [%1], 16;" :: "r"(dst_smem), "l"(src_gmem));
}
#define CP_COMMIT() asm volatile("cp.async.commit_group;" ::: "memory")
#define CP_WAIT1()  asm volatile("cp.async.wait_group 1;" ::: "memory")
#define CP_WAIT0()  asm volatile("cp.async.wait_group 0;" ::: "memory")

__device__ __forceinline__ void mma_bf16(float* c, const uint32_t* a, uint32_t b0, uint32_t b1) {
    asm volatile(
        "mma.sync.aligned.m16n8k16.row.col.f32.bf16.bf16.f32 "
        "{%0,%1,%2,%3},{%4,%5,%6,%7},{%8,%9},{%0,%1,%2,%3};"
        : "+f"(c[0]), "+f"(c[1]), "+f"(c[2]), "+f"(c[3])
        : "r"(a[0]), "r"(a[1]), "r"(a[2]), "r"(a[3]), "r"(b0), "r"(b1));
}

// byte offset of element (kg, n) inside g_yaugB (fragment-register layout)
__device__ __forceinline__ uint32_t b_offset(int kg, int n) {
    int gc  = kg >> 5;            // global chunk
    int k16 = (kg >> 4) & 1;      // k16 fragment within chunk
    int kl  = kg & 15;            // k within fragment
    int nt  = n >> 3;
    int n8  = n & 7;
    int lane = n8 * 4 + ((kl & 7) >> 1);
    return (uint32_t)(((gc * 2 + k16) * NTILES + nt) * 256 + lane * 8
                      + ((kl >> 3) & 1) * 4 + (kl & 1) * 2);
}

// ---------------- SMEM layout (bytes) ----------------
#define SMEM_A0   0
#define SMEM_A1   (TILE_M * ASTRIDE * 4)               // 20480
#define SMEM_B0   (2 * TILE_M * ASTRIDE * 4)           // 40960
#define SMEM_B1   (SMEM_B0 + BCH_BYTES)                // 45568
#define SMEM_RED  (SMEM_B1 + BCH_BYTES)                // 50176
#define SMEM_TOTAL (SMEM_RED + 64)                     // 50240

// ---------------- prep: sq + fragment-packed bf16 Yaug, one warp per row ----------------
__global__ void prep(const float* __restrict__ Y) {
    int w    = (blockIdx.x * blockDim.x + threadIdx.x) >> 5;
    int lane = threadIdx.x & 31;
    if (w >= NROW) return;
    if (w == 0 && lane == 0) g_cnt = 0;   // harness-robust counter reset (prep runs before main)

    const float* yr = Y + (size_t)w * KDIM;
    float v0 = yr[lane], v1 = yr[lane + 32];
    float s = v0 * v0 + v1 * v1;
#pragma unroll
    for (int o = 16; o; o >>= 1) s += __shfl_xor_sync(0xffffffffu, s, o);  // all lanes get sum
    if (lane == 0) g_sq[w] = s;

    *reinterpret_cast<__nv_bfloat16*>(g_yaugB + b_offset(w, lane))      = __float2bfloat16_rn(v0);
    *reinterpret_cast<__nv_bfloat16*>(g_yaugB + b_offset(w, lane + 32)) = __float2bfloat16_rn(v1);
    if (lane < 8) {
        float v = (lane == 0) ? 1.0f : (lane == 1) ? s : 0.0f;
        *reinterpret_cast<__nv_bfloat16*>(g_yaugB + b_offset(w, 64 + lane)) = __float2bfloat16_rn(v);
    }
}

// ---------------- main kernel ----------------
__global__ __launch_bounds__(NTHREADS)
void spectral_main(const float* __restrict__ W, const float* __restrict__ Y,
                   float* __restrict__ out) {
    extern __shared__ __align__(16) char smem[];
    float* smf = reinterpret_cast<float*>(smem);
    const uint32_t sb = smem_to_u32(smem);

    const int tid  = threadIdx.x;
    const int wid  = tid >> 5;
    const int lane = tid & 31;
    const int g    = lane >> 2;
    const int tg   = lane & 3;
    const int m0   = blockIdx.x * TILE_M;
    const int kbase = blockIdx.y * KSPLIT;

    float acc[2][NTILES][4];
#pragma unroll
    for (int mf = 0; mf < 2; ++mf)
#pragma unroll
        for (int nt = 0; nt < NTILES; ++nt)
#pragma unroll
            for (int q = 0; q < 4; ++q) acc[mf][nt][q] = 0.0f;

    auto load_chunk = [&](int t) {
        const uint32_t ab = sb + ((t & 1) ? SMEM_A1 : SMEM_A0);
        const uint32_t bb = sb + ((t & 1) ? SMEM_B1 : SMEM_B0);
        const int k0 = kbase + t * KC;
        // A: W tile 128 x 32 fp32 = 1024 float4
#pragma unroll
        for (int j = 0; j < 8; ++j) {
            int f = tid + j * NTHREADS;
            int r = f >> 3, c4 = f & 7;
            cpa16(ab + (uint32_t)(r * ASTRIDE + c4 * 4) * 4,
                  W + (size_t)(m0 + r) * NROW + k0 + c4 * 4);
        }
        // B: fragment-packed chunk, 4608 B = 288 float4 (L2-resident)
        const unsigned char* bsrc = g_yaugB + (size_t)(k0 >> 5) * BCH_BYTES;
#pragma unroll
        for (int j = 0; j < 3; ++j) {
            int f = tid + j * NTHREADS;
            if (f < 288) cpa16(bb + (uint32_t)f * 16, bsrc + (size_t)f * 16);
        }
        CP_COMMIT();
    };

    load_chunk(0);

    for (int t = 0; t < NCHUNK; ++t) {
        if (t + 1 < NCHUNK) { load_chunk(t + 1); CP_WAIT1(); }
        else                { CP_WAIT0(); }
        __syncthreads();

        const float* abuf = smf + ((t & 1) ? SMEM_A1 : SMEM_A0) / 4;
        const char*  bbuf = smem + ((t & 1) ? SMEM_B1 : SMEM_B0);

#pragma unroll
        for (int ks = 0; ks < 2; ++ks) {
            uint32_t a[2][4];
#pragma unroll
            for (int mf = 0; mf < 2; ++mf) {
                int rb = wid * 32 + mf * 16;
                int cb = ks * 16 + tg * 2;
                float2 v0 = *reinterpret_cast<const float2*>(abuf + (rb + g)     * ASTRIDE + cb);
                float2 v1 = *reinterpret_cast<const float2*>(abuf + (rb + g + 8) * ASTRIDE + cb);
                float2 v2 = *reinterpret_cast<const float2*>(abuf + (rb + g)     * ASTRIDE + cb + 8);
                float2 v3 = *reinterpret_cast<const float2*>(abuf + (rb + g + 8) * ASTRIDE + cb + 8);
                a[mf][0] = pack_bf16x2(v0.x, v0.y);
                a[mf][1] = pack_bf16x2(v1.x, v1.y);
                a[mf][2] = pack_bf16x2(v2.x, v2.y);
                a[mf][3] = pack_bf16x2(v3.x, v3.y);
            }
#pragma unroll
            for (int nt = 0; nt < NTILES; ++nt) {
                uint2 b = *reinterpret_cast<const uint2*>(
                    bbuf + (ks * NTILES + nt) * 256 + lane * 8);
                mma_bf16(acc[0][nt], a[0], b.x, b.y);
                mma_bf16(acc[1][nt], a[1], b.x, b.y);
            }
        }
        __syncthreads();
    }

    // ---- epilogue: contract Z fragments against coefficients ----
    float partial = 0.0f;
#pragma unroll
    for (int mf = 0; mf < 2; ++mf) {
#pragma unroll
        for (int half = 0; half < 2; ++half) {
            int i = m0 + wid * 32 + mf * 16 + half * 8 + g;
            const float* yr = Y + (size_t)i * KDIM;
            float s = 0.0f;
#pragma unroll
            for (int nt = 0; nt < 8; ++nt) {
                int col = nt * 8 + tg * 2;
                s = fmaf(yr[col],     acc[mf][nt][half * 2 + 0], s);
                s = fmaf(yr[col + 1], acc[mf][nt][half * 2 + 1], s);
            }
            float e = -2.0f * s;
            if (tg == 0) {
                e = fmaf(g_sq[i], acc[mf][8][half * 2 + 0], e);
                e += acc[mf][8][half * 2 + 1];
            }
            partial += e;
        }
    }
#pragma unroll
    for (int o = 16; o; o >>= 1) partial += __shfl_xor_sync(0xffffffffu, partial, o);
    float* red = reinterpret_cast<float*>(smem + SMEM_RED);
    if (lane == 0) red[wid] = partial;
    __syncthreads();

    // ---- last-block deterministic final reduction ----
    volatile int* flag = reinterpret_cast<volatile int*>(smem + SMEM_RED + 32);
    if (tid == 0) {
        g_part[blockIdx.y * MTILES + blockIdx.x] = red[0] + red[1] + red[2] + red[3];
        __threadfence();
        unsigned int old = atomicAdd(&g_cnt, 1u);
        *flag = (old == NPART - 1) ? 1 : 0;
    }
    __syncthreads();
    if (*flag) {
        __threadfence();
        float s = g_part[tid] + g_part[tid + 128] + g_part[tid + 256] + g_part[tid + 384];
#pragma unroll
        for (int o = 16; o; o >>= 1) s += __shfl_xor_sync(0xffffffffu, s, o);
        if (lane == 0) red[wid] = s;
        __syncthreads();
        if (tid == 0) {
            out[0] = (red[0] + red[1] + red[2] + red[3]) * (1.0f / (2.0f * (float)NROW));
            g_cnt = 0;
        }
    }
}

// ---------------- launch ----------------
extern "C" void kernel_launch(void* const* d_in, const int* in_sizes, int n_in,
                              void* d_out, int out_size) {
    const float* W;
    const float* Y;
    if (in_sizes[0] == NROW * NROW) {
        W = (const float*)d_in[0];
        Y = (const float*)d_in[1];
    } else {
        Y = (const float*)d_in[0];
        W = (const float*)d_in[1];
    }
    cudaFuncSetAttribute(spectral_main, cudaFuncAttributeMaxDynamicSharedMemorySize, SMEM_TOTAL);

    prep<<<NROW / 8, 256>>>(Y);
    spectral_main<<<dim3(MTILES, SPLITS), NTHREADS, SMEM_TOTAL>>>(W, Y, (float*)d_out);
}